// round 11
// baseline (speedup 1.0000x reference)
#include <cuda_runtime.h>
#include <cuda_bf16.h>
#include <cuda_fp16.h>
#include <cstdint>

#define NB   32
#define CC   256
#define HH   56
#define WW   56
#define HW   3136
#define NHW  100352
#define COUT 256
#define KK   9
#define CIN_K 2304
#define PADW 58
#define XBP_PIX 3584
#define NBH  24         // images 0..23 bf16-f32 path; 24..31 fp16-f16 path
#define NH8  (NB - NBH)

// ---------------- scratch (device globals; zero-init => padding stays 0) -------
__device__ float g_psum[CC * 8 * 2];
__device__ float g_scale[CC];
__device__ float g_shift[CC];
__device__ float g_m[NHW];
__device__ float g_betamap[NHW];
__device__ float g_alpha[COUT];
__device__ __nv_bfloat16 g_xbf[(size_t)NBH * XBP_PIX * CC];
__device__ __half        g_xh [(size_t)NH8 * XBP_PIX * CC];
__device__ __nv_bfloat16 g_wbf[(size_t)COUT * CIN_K];
__device__ __half        g_wh [(size_t)COUT * CIN_K];

// ---------------- helpers ----------------
__device__ __forceinline__ uint32_t smem_u32(const void* p) {
    uint32_t a;
    asm("{ .reg .u64 t; cvta.to.shared.u64 t, %1; cvt.u32.u64 %0, t; }" : "=r"(a) : "l"(p));
    return a;
}
#define SWZ(o) ((o) ^ (((o) >> 3) & 0x70))
__device__ __forceinline__ void cp16(uint32_t dst, const void* src) {
    asm volatile("cp.async.cg.shared.global [%0], [%1], 16;" :: "r"(dst), "l"(src));
}
__device__ __forceinline__ void ldsm4(uint32_t* r, uint32_t addr) {
    asm volatile("ldmatrix.sync.aligned.m8n8.x4.shared.b16 {%0,%1,%2,%3}, [%4];"
                 : "=r"(r[0]), "=r"(r[1]), "=r"(r[2]), "=r"(r[3]) : "r"(addr));
}
__device__ __forceinline__ void mma_bf16(float* d, const uint32_t* a, uint32_t b0, uint32_t b1) {
    asm volatile("mma.sync.aligned.m16n8k16.row.col.f32.bf16.bf16.f32 "
                 "{%0,%1,%2,%3}, {%4,%5,%6,%7}, {%8,%9}, {%0,%1,%2,%3};"
                 : "+f"(d[0]), "+f"(d[1]), "+f"(d[2]), "+f"(d[3])
                 : "r"(a[0]), "r"(a[1]), "r"(a[2]), "r"(a[3]), "r"(b0), "r"(b1));
}
__device__ __forceinline__ void mma_f16acc(uint32_t* d, const uint32_t* a, uint32_t b0, uint32_t b1) {
    asm volatile("mma.sync.aligned.m16n8k16.row.col.f16.f16.f16.f16 "
                 "{%0,%1}, {%2,%3,%4,%5}, {%6,%7}, {%0,%1};"
                 : "+r"(d[0]), "+r"(d[1])
                 : "r"(a[0]), "r"(a[1]), "r"(a[2]), "r"(a[3]), "r"(b0), "r"(b1));
}

// ---------------- K1a/K1b: BN batch stats (two-phase) ----------------
__global__ void stats_part_kernel(const float* __restrict__ x) {
    int c = blockIdx.x, sl = blockIdx.y, tid = threadIdx.x;
    float s = 0.f, s2 = 0.f;
    for (int n = sl * 4; n < sl * 4 + 4; n++) {
        const float* p = x + ((size_t)n * CC + c) * HW;
        for (int i = tid; i < HW; i += blockDim.x) { float v = p[i]; s += v; s2 += v * v; }
    }
    __shared__ float sh[256], sh2[256];
    sh[tid] = s; sh2[tid] = s2; __syncthreads();
    for (int off = 128; off > 0; off >>= 1) {
        if (tid < off) { sh[tid] += sh[tid + off]; sh2[tid] += sh2[tid + off]; }
        __syncthreads();
    }
    if (tid == 0) { g_psum[(c * 8 + sl) * 2] = sh[0]; g_psum[(c * 8 + sl) * 2 + 1] = sh2[0]; }
}
__global__ void stats_final_kernel(const float* __restrict__ gamma,
                                   const float* __restrict__ beta_bn) {
    int c = threadIdx.x;
    float s = 0.f, s2 = 0.f;
    #pragma unroll
    for (int i = 0; i < 8; i++) { s += g_psum[(c * 8 + i) * 2]; s2 += g_psum[(c * 8 + i) * 2 + 1]; }
    float mu  = s * (1.0f / (float)NHW);
    float var = s2 * (1.0f / (float)NHW) - mu * mu;
    float inv = rsqrtf(var + 1e-4f);
    float sc  = gamma[c] * inv;
    g_scale[c] = sc;
    g_shift[c] = beta_bn[c] - mu * sc;
}

// ------- K2: binarize -> bf16 (n<24) / fp16 (n>=24), + |xn| mean ---------------
__global__ void binact_pack_kernel(const float* __restrict__ x) {
    int gp = blockIdx.x * blockDim.x + threadIdx.x;
    if (gp >= NHW) return;
    int n = gp / HW, p = gp % HW;
    int h = p / WW, w = p % WW;
    const float* xp = x + (size_t)n * CC * HW + p;
    float acc = 0.f;
    if (n < NBH) {
        __nv_bfloat16* dst = g_xbf + ((size_t)n * XBP_PIX + (h + 1) * PADW + (w + 1)) * CC;
        for (int c0 = 0; c0 < CC; c0 += 32) {
            __nv_bfloat16 bbuf[32];
            #pragma unroll
            for (int cc = 0; cc < 32; cc++) {
                int c = c0 + cc;
                float v = xp[(size_t)c * HW] * g_scale[c] + g_shift[c];
                acc += fabsf(v);
                float s = (v > 0.f) ? 1.f : ((v < 0.f) ? -1.f : 0.f);
                bbuf[cc] = __float2bfloat16(s);
            }
            #pragma unroll
            for (int i = 0; i < 4; i++)
                reinterpret_cast<uint4*>(dst + c0)[i] = reinterpret_cast<uint4*>(bbuf)[i];
        }
    } else {
        __half* dst = g_xh + (((size_t)(n - NBH)) * XBP_PIX + (h + 1) * PADW + (w + 1)) * CC;
        for (int c0 = 0; c0 < CC; c0 += 32) {
            __half bbuf[32];
            #pragma unroll
            for (int cc = 0; cc < 32; cc++) {
                int c = c0 + cc;
                float v = xp[(size_t)c * HW] * g_scale[c] + g_shift[c];
                acc += fabsf(v);
                float s = (v > 0.f) ? 1.f : ((v < 0.f) ? -1.f : 0.f);
                bbuf[cc] = __float2half(s);
            }
            #pragma unroll
            for (int i = 0; i < 4; i++)
                reinterpret_cast<uint4*>(dst + c0)[i] = reinterpret_cast<uint4*>(bbuf)[i];
        }
    }
    g_m[gp] = acc * (1.0f / (float)CC);
}

// ------- K3: box filter + weight prep (bf16 + fp16, tap-major) + alpha ---------
#define BOX_BLOCKS ((NHW + 255) / 256)
__global__ void boxwprep_kernel(const float* __restrict__ Wt) {
    if (blockIdx.x < BOX_BLOCKS) {
        int gp = blockIdx.x * blockDim.x + threadIdx.x;
        if (gp >= NHW) return;
        int n = gp / HW, p = gp % HW;
        int h = p / WW, w = p % WW;
        const float* mp = g_m + (size_t)n * HW;
        float s = 0.f;
        #pragma unroll
        for (int dh = -1; dh <= 1; dh++)
            #pragma unroll
            for (int dw = -1; dw <= 1; dw++) {
                int hh = h + dh, ww2 = w + dw;
                if (hh >= 0 && hh < HH && ww2 >= 0 && ww2 < WW) s += mp[hh * WW + ww2];
            }
        g_betamap[gp] = s * (1.0f / 9.0f);
    } else {
        int co = blockIdx.x - BOX_BLOCKS, tid = threadIdx.x;
        const float* wp = Wt + (size_t)co * CIN_K;
        float s = 0.f;
        for (int i = tid; i < CIN_K; i += blockDim.x) {
            float v = wp[i];
            s += fabsf(v);
            int ci = i / KK, tap = i % KK;
            float sv = (v > 0.f) ? 1.f : ((v < 0.f) ? -1.f : 0.f);
            g_wbf[(size_t)co * CIN_K + tap * CC + ci] = __float2bfloat16(sv);
            g_wh [(size_t)co * CIN_K + tap * CC + ci] = __float2half(sv);
        }
        __shared__ float sh[256];
        sh[tid] = s; __syncthreads();
        for (int off = 128; off > 0; off >>= 1) {
            if (tid < off) sh[tid] += sh[tid + off];
            __syncthreads();
        }
        if (tid == 0) g_alpha[co] = sh[0] * (1.0f / (float)CIN_K);
    }
}

// ------ shared conv layout constants ------
#define STAGE 32768          // A 16KB + B 16KB  (64ch x 2B = 128B rows, both paths)
#define OFF_B 16384
#define NSTAGE 3
#define NCH 36               // 9 taps x 4 chunks of 64 channels
#define OFF_AB (NSTAGE * STAGE)
#define SMEM_TOT (OFF_AB + 1024)

__device__ __forceinline__ void load_stage16(uint32_t sbase, const char* aBase,
                                             const char* bBase, int chunk, int tid) {
    int t = chunk >> 2, q = chunk & 3;                   // tap, 64-channel group
    int off_t = (t / 3) * PADW + (t % 3);
    const char* a0 = aBase + ((size_t)off_t * CC + q * 64) * 2;
    const char* bs = bBase + ((size_t)t * CC + q * 64) * 2;
    #pragma unroll
    for (int i = 0; i < 4; i++) {       // A: 128 rows x 128B
        int slot = tid + 256 * i; int row = slot >> 3, c16 = slot & 7;
        cp16(sbase + SWZ(row * 128 + c16 * 16), a0 + (size_t)row * CC * 2 + c16 * 16);
    }
    #pragma unroll
    for (int i = 0; i < 4; i++) {       // B: 128 couts x 128B
        int slot = tid + 256 * i; int row = slot >> 3, c16 = slot & 7;
        cp16(sbase + OFF_B + SWZ(row * 128 + c16 * 16), bs + (size_t)row * CIN_K * 2 + c16 * 16);
    }
    asm volatile("cp.async.commit_group;" ::: "memory");
}

// ------ K4: bf16-f32 conv (images 0..23), CTA 128px x 128co, 2 CTA/SM ----------
__global__ void __launch_bounds__(256, 2)
conv_bf16_kernel(const float* __restrict__ bias, float* __restrict__ out) {
    extern __shared__ __align__(1024) char smem[];
    uint32_t sm = smem_u32(smem);
    int tid = threadIdx.x, wid = tid >> 5, lane = tid & 31;
    int b0  = blockIdx.x * 128;
    int cob = blockIdx.y * 128;
    int n   = blockIdx.z;
    int wm = wid & 3, wn = wid >> 2;

    float* s_bias  = (float*)(smem + OFF_AB);
    float* s_alpha = (float*)(smem + OFF_AB + 512);
    if (tid < 128) { s_bias[tid] = bias[cob + tid]; s_alpha[tid] = g_alpha[cob + tid]; }

    const char* aBase = (const char*)(g_xbf + ((size_t)n * XBP_PIX + b0) * CC);
    const char* bBase = (const char*)(g_wbf + (size_t)cob * CIN_K);

    int lrow = (lane & 7) + ((lane >> 3) & 1) * 8;
    uint32_t ltb = (uint32_t)((lane >> 4) * 16);
    uint32_t xk  = (uint32_t)((lane & 7) << 4);
    uint32_t aA[2], aB[4];
    #pragma unroll
    for (int mi = 0; mi < 2; mi++) aA[mi] = (uint32_t)((wm * 32 + mi * 16 + lrow) * 128);
    #pragma unroll
    for (int nj = 0; nj < 4; nj++) aB[nj] = (uint32_t)(OFF_B + (wn * 64 + nj * 16 + lrow) * 128);

    float acc[2][8][4];
    #pragma unroll
    for (int mi = 0; mi < 2; mi++)
        #pragma unroll
        for (int ni = 0; ni < 8; ni++)
            #pragma unroll
            for (int j = 0; j < 4; j++) acc[mi][ni][j] = 0.f;

    load_stage16(sm + 0 * STAGE, aBase, bBase, 0, tid);
    load_stage16(sm + 1 * STAGE, aBase, bBase, 1, tid);

    int slot = 0;
    for (int k = 0; k < NCH; k++) {
        if (k < NCH - 1) asm volatile("cp.async.wait_group 1;" ::: "memory");
        else             asm volatile("cp.async.wait_group 0;" ::: "memory");
        __syncthreads();
        if (k + 2 < NCH) {
            int s2 = slot + 2; if (s2 >= NSTAGE) s2 -= NSTAGE;
            load_stage16(sm + s2 * STAGE, aBase, bBase, k + 2, tid);
        }
        uint32_t sb = sm + slot * STAGE;
        #pragma unroll
        for (int ks = 0; ks < 4; ks++) {
            uint32_t off = (((uint32_t)(ks << 5)) | ltb) ^ xk;
            uint32_t a[2][4], bf[4][4];
            ldsm4(a[0], sb + aA[0] + off);
            ldsm4(a[1], sb + aA[1] + off);
            #pragma unroll
            for (int nj = 0; nj < 4; nj++) ldsm4(bf[nj], sb + aB[nj] + off);
            #pragma unroll
            for (int mi = 0; mi < 2; mi++)
                #pragma unroll
                for (int ni = 0; ni < 8; ni++) {
                    int nj = ni >> 1, sel = ni & 1;
                    mma_bf16(acc[mi][ni], a[mi], bf[nj][sel], bf[nj][sel + 2]);
                }
        }
        slot = (slot + 1 == NSTAGE) ? 0 : slot + 1;
    }

    #pragma unroll
    for (int mi = 0; mi < 2; mi++)
        #pragma unroll
        for (int half = 0; half < 2; half++) {
            int b = b0 + wm * 32 + mi * 16 + (lane >> 2) + half * 8;
            int h = b / PADW, wp = b % PADW;
            bool valid = (h < HH) && (wp < WW);
            float bm = valid ? g_betamap[(size_t)n * HW + h * WW + wp] : 0.f;
            float* obase = out + (size_t)n * COUT * HW + h * WW + wp;
            if (valid) {
                #pragma unroll
                for (int ni = 0; ni < 8; ni++)
                    #pragma unroll
                    for (int j2 = 0; j2 < 2; j2++) {
                        int col = wn * 64 + ni * 8 + 2 * (lane & 3) + j2;
                        float v = (acc[mi][ni][half * 2 + j2] + s_bias[col])
                                  * bm * s_alpha[col];
                        obase[(size_t)(cob + col) * HW] = fmaxf(v, 0.f);
                    }
            }
        }
}

// ------ K5: fp16-f16 conv (images 24..31), same structure ----------------------
__global__ void __launch_bounds__(256, 2)
conv_f16_kernel(const float* __restrict__ bias, float* __restrict__ out) {
    extern __shared__ __align__(1024) char smem[];
    uint32_t sm = smem_u32(smem);
    int tid = threadIdx.x, wid = tid >> 5, lane = tid & 31;
    int b0  = blockIdx.x * 128;
    int cob = blockIdx.y * 128;
    int n   = blockIdx.z + NBH;
    int wm = wid & 3, wn = wid >> 2;

    float* s_bias  = (float*)(smem + OFF_AB);
    float* s_alpha = (float*)(smem + OFF_AB + 512);
    if (tid < 128) { s_bias[tid] = bias[cob + tid]; s_alpha[tid] = g_alpha[cob + tid]; }

    const char* aBase = (const char*)(g_xh + ((size_t)(n - NBH) * XBP_PIX + b0) * CC);
    const char* bBase = (const char*)(g_wh + (size_t)cob * CIN_K);

    int lrow = (lane & 7) + ((lane >> 3) & 1) * 8;
    uint32_t ltb = (uint32_t)((lane >> 4) * 16);
    uint32_t xk  = (uint32_t)((lane & 7) << 4);
    uint32_t aA[2], aB[4];
    #pragma unroll
    for (int mi = 0; mi < 2; mi++) aA[mi] = (uint32_t)((wm * 32 + mi * 16 + lrow) * 128);
    #pragma unroll
    for (int nj = 0; nj < 4; nj++) aB[nj] = (uint32_t)(OFF_B + (wn * 64 + nj * 16 + lrow) * 128);

    uint32_t acc[2][8][2];     // f16x2 accumulators
    #pragma unroll
    for (int mi = 0; mi < 2; mi++)
        #pragma unroll
        for (int ni = 0; ni < 8; ni++) { acc[mi][ni][0] = 0u; acc[mi][ni][1] = 0u; }

    load_stage16(sm + 0 * STAGE, aBase, bBase, 0, tid);
    load_stage16(sm + 1 * STAGE, aBase, bBase, 1, tid);

    int slot = 0;
    for (int k = 0; k < NCH; k++) {
        if (k < NCH - 1) asm volatile("cp.async.wait_group 1;" ::: "memory");
        else             asm volatile("cp.async.wait_group 0;" ::: "memory");
        __syncthreads();
        if (k + 2 < NCH) {
            int s2 = slot + 2; if (s2 >= NSTAGE) s2 -= NSTAGE;
            load_stage16(sm + s2 * STAGE, aBase, bBase, k + 2, tid);
        }
        uint32_t sb = sm + slot * STAGE;
        #pragma unroll
        for (int ks = 0; ks < 4; ks++) {
            uint32_t off = (((uint32_t)(ks << 5)) | ltb) ^ xk;
            uint32_t a[2][4], bf[4][4];
            ldsm4(a[0], sb + aA[0] + off);
            ldsm4(a[1], sb + aA[1] + off);
            #pragma unroll
            for (int nj = 0; nj < 4; nj++) ldsm4(bf[nj], sb + aB[nj] + off);
            #pragma unroll
            for (int mi = 0; mi < 2; mi++)
                #pragma unroll
                for (int ni = 0; ni < 8; ni++) {
                    int nj = ni >> 1, sel = ni & 1;
                    mma_f16acc(acc[mi][ni], a[mi], bf[nj][sel], bf[nj][sel + 2]);
                }
        }
        slot = (slot + 1 == NSTAGE) ? 0 : slot + 1;
    }

    // epilogue: f16 d-layout: reg r (r=0:rows lane>>2, r=1:+8), halves = col pair
    #pragma unroll
    for (int mi = 0; mi < 2; mi++)
        #pragma unroll
        for (int half = 0; half < 2; half++) {
            int b = b0 + wm * 32 + mi * 16 + (lane >> 2) + half * 8;
            int h = b / PADW, wp = b % PADW;
            bool valid = (h < HH) && (wp < WW);
            float bm = valid ? g_betamap[(size_t)n * HW + h * WW + wp] : 0.f;
            float* obase = out + (size_t)n * COUT * HW + h * WW + wp;
            if (valid) {
                #pragma unroll
                for (int ni = 0; ni < 8; ni++) {
                    __half2 hv = *reinterpret_cast<__half2*>(&acc[mi][ni][half]);
                    float2 fv = __half22float2(hv);
                    #pragma unroll
                    for (int j2 = 0; j2 < 2; j2++) {
                        int col = wn * 64 + ni * 8 + 2 * (lane & 3) + j2;
                        float dv = (j2 == 0) ? fv.x : fv.y;
                        float v = (dv + s_bias[col]) * bm * s_alpha[col];
                        obase[(size_t)(cob + col) * HW] = fmaxf(v, 0.f);
                    }
                }
            }
        }
}

// ---------------- launcher ----------------
extern "C" void kernel_launch(void* const* d_in, const int* in_sizes, int n_in,
                              void* d_out, int out_size) {
    const float* x       = (const float*)d_in[0];
    const float* gamma   = (const float*)d_in[1];
    const float* beta_bn = (const float*)d_in[2];
    const float* Wt      = (const float*)d_in[3];
    const float* b       = (const float*)d_in[4];
    float* out = (float*)d_out;

    cudaFuncSetAttribute(conv_bf16_kernel,
                         cudaFuncAttributeMaxDynamicSharedMemorySize, SMEM_TOT);
    cudaFuncSetAttribute(conv_f16_kernel,
                         cudaFuncAttributeMaxDynamicSharedMemorySize, SMEM_TOT);

    stats_part_kernel<<<dim3(CC, 8), 256>>>(x);
    stats_final_kernel<<<1, 256>>>(gamma, beta_bn);
    binact_pack_kernel<<<(NHW + 255) / 256, 256>>>(x);
    boxwprep_kernel<<<BOX_BLOCKS + COUT, 256>>>(Wt);
    conv_bf16_kernel<<<dim3(27, 2, NBH), 256, SMEM_TOT>>>(b, out);
    conv_f16_kernel<<<dim3(27, 2, NH8), 256, SMEM_TOT>>>(b, out);
}

// round 12
// speedup vs baseline: 1.0452x; 1.0452x over previous
#include <cuda_runtime.h>
#include <cuda_bf16.h>
#include <cstdint>

#define NB   32
#define CC   256
#define HH   56
#define WW   56
#define HW   3136
#define NHW  100352
#define COUT 256
#define KK   9
#define CIN_K 2304
#define PADW 58
#define XBP_PIX 3584

// ---------------- scratch (device globals; zero-init => padding stays 0) -------
__device__ float g_psum[CC * 8 * 2];
__device__ float g_m[NHW];
__device__ float g_betamap[NHW];
__device__ float g_alpha[COUT];
__device__ __nv_bfloat16 g_xbf[(size_t)NB * XBP_PIX * CC];   // [n][padded pix][c]
__device__ __nv_bfloat16 g_wbf[(size_t)COUT * CIN_K];        // [cout][tap*256+ci]

// ---------------- helpers ----------------
__device__ __forceinline__ uint32_t smem_u32(const void* p) {
    uint32_t a;
    asm("{ .reg .u64 t; cvta.to.shared.u64 t, %1; cvt.u32.u64 %0, t; }" : "=r"(a) : "l"(p));
    return a;
}
#define SWZ(o) ((o) ^ (((o) >> 3) & 0x70))
__device__ __forceinline__ void cp16(uint32_t dst, const void* src) {
    asm volatile("cp.async.cg.shared.global [%0], [%1], 16;" :: "r"(dst), "l"(src));
}
__device__ __forceinline__ void ldsm4(uint32_t* r, uint32_t addr) {
    asm volatile("ldmatrix.sync.aligned.m8n8.x4.shared.b16 {%0,%1,%2,%3}, [%4];"
                 : "=r"(r[0]), "=r"(r[1]), "=r"(r[2]), "=r"(r[3]) : "r"(addr));
}
__device__ __forceinline__ void mma_bf16(float* d, const uint32_t* a, uint32_t b0, uint32_t b1) {
    asm volatile("mma.sync.aligned.m16n8k16.row.col.f32.bf16.bf16.f32 "
                 "{%0,%1,%2,%3}, {%4,%5,%6,%7}, {%8,%9}, {%0,%1,%2,%3};"
                 : "+f"(d[0]), "+f"(d[1]), "+f"(d[2]), "+f"(d[3])
                 : "r"(a[0]), "r"(a[1]), "r"(a[2]), "r"(a[3]), "r"(b0), "r"(b1));
}

// ---------------- K1: BN batch partial sums ----------------
__global__ void stats_part_kernel(const float* __restrict__ x) {
    int c = blockIdx.x, sl = blockIdx.y, tid = threadIdx.x;
    float s = 0.f, s2 = 0.f;
    for (int n = sl * 4; n < sl * 4 + 4; n++) {
        const float* p = x + ((size_t)n * CC + c) * HW;
        for (int i = tid; i < HW; i += blockDim.x) { float v = p[i]; s += v; s2 += v * v; }
    }
    __shared__ float sh[256], sh2[256];
    sh[tid] = s; sh2[tid] = s2; __syncthreads();
    for (int off = 128; off > 0; off >>= 1) {
        if (tid < off) { sh[tid] += sh[tid + off]; sh2[tid] += sh2[tid + off]; }
        __syncthreads();
    }
    if (tid == 0) { g_psum[(c * 8 + sl) * 2] = sh[0]; g_psum[(c * 8 + sl) * 2 + 1] = sh2[0]; }
}

// ------- K2: finalize stats in-block, binarize -> bf16 padded, + |xn| mean -----
__global__ void binact_pack_kernel(const float* __restrict__ x,
                                   const float* __restrict__ gamma,
                                   const float* __restrict__ beta_bn) {
    __shared__ float s_scale[CC], s_shift[CC];
    {
        int c = threadIdx.x;
        float s = 0.f, s2 = 0.f;
        #pragma unroll
        for (int i = 0; i < 8; i++) {
            s  += g_psum[(c * 8 + i) * 2];
            s2 += g_psum[(c * 8 + i) * 2 + 1];
        }
        float mu  = s * (1.0f / (float)NHW);
        float var = s2 * (1.0f / (float)NHW) - mu * mu;
        float inv = rsqrtf(var + 1e-4f);
        float sc  = gamma[c] * inv;
        s_scale[c] = sc;
        s_shift[c] = beta_bn[c] - mu * sc;
    }
    __syncthreads();

    int gp = blockIdx.x * blockDim.x + threadIdx.x;
    if (gp >= NHW) return;
    int n = gp / HW, p = gp % HW;
    int h = p / WW, w = p % WW;
    const float* xp = x + (size_t)n * CC * HW + p;
    __nv_bfloat16* dst = g_xbf + ((size_t)n * XBP_PIX + (h + 1) * PADW + (w + 1)) * CC;
    float acc = 0.f;
    for (int c0 = 0; c0 < CC; c0 += 64) {
        __nv_bfloat16 bbuf[64];
        #pragma unroll
        for (int cc = 0; cc < 64; cc++) {
            int c = c0 + cc;
            float v = xp[(size_t)c * HW] * s_scale[c] + s_shift[c];
            acc += fabsf(v);
            float s = (v > 0.f) ? 1.f : ((v < 0.f) ? -1.f : 0.f);
            bbuf[cc] = __float2bfloat16(s);
        }
        #pragma unroll
        for (int i = 0; i < 8; i++)
            reinterpret_cast<uint4*>(dst + c0)[i] = reinterpret_cast<uint4*>(bbuf)[i];
    }
    g_m[gp] = acc * (1.0f / (float)CC);
}

// ------- K3: box filter + weight prep (bf16, tap-major) + alpha ----------------
#define BOX_BLOCKS ((NHW + 255) / 256)
__global__ void boxwprep_kernel(const float* __restrict__ Wt) {
    if (blockIdx.x < BOX_BLOCKS) {
        int gp = blockIdx.x * blockDim.x + threadIdx.x;
        if (gp >= NHW) return;
        int n = gp / HW, p = gp % HW;
        int h = p / WW, w = p % WW;
        const float* mp = g_m + (size_t)n * HW;
        float s = 0.f;
        #pragma unroll
        for (int dh = -1; dh <= 1; dh++)
            #pragma unroll
            for (int dw = -1; dw <= 1; dw++) {
                int hh = h + dh, ww2 = w + dw;
                if (hh >= 0 && hh < HH && ww2 >= 0 && ww2 < WW) s += mp[hh * WW + ww2];
            }
        g_betamap[gp] = s * (1.0f / 9.0f);
    } else {
        int co = blockIdx.x - BOX_BLOCKS, tid = threadIdx.x;
        const float* wp = Wt + (size_t)co * CIN_K;
        float s = 0.f;
        for (int i = tid; i < CIN_K; i += blockDim.x) {
            float v = wp[i];
            s += fabsf(v);
            int ci = i / KK, tap = i % KK;
            float sv = (v > 0.f) ? 1.f : ((v < 0.f) ? -1.f : 0.f);
            g_wbf[(size_t)co * CIN_K + tap * CC + ci] = __float2bfloat16(sv);
        }
        __shared__ float sh[256];
        sh[tid] = s; __syncthreads();
        for (int off = 128; off > 0; off >>= 1) {
            if (tid < off) sh[tid] += sh[tid + off];
            __syncthreads();
        }
        if (tid == 0) g_alpha[co] = sh[0] * (1.0f / (float)CIN_K);
    }
}

// ------ K4: bf16 HMMA conv, CTA 128px x 128co, 2 CTAs/SM, 3-stage --------------
#define STAGE 32768          // A 16KB + B 16KB
#define OFF_B 16384
#define NSTAGE 3
#define NCH 36               // 9 taps x 4 chunks of 64 channels
#define OFF_AB (NSTAGE * STAGE)
#define SMEM_TOT (OFF_AB + 1024)

__device__ __forceinline__ void load_stage_bf(uint32_t sbase, const __nv_bfloat16* aBase,
                                              const __nv_bfloat16* bBase, int chunk, int tid) {
    int t = chunk >> 2, q = chunk & 3;                   // tap, 64-channel group
    int off_t = (t / 3) * PADW + (t % 3);
    const __nv_bfloat16* a0 = aBase + (size_t)off_t * CC + q * 64;
    const __nv_bfloat16* bs = bBase + t * CC + q * 64;
    #pragma unroll
    for (int i = 0; i < 4; i++) {       // A: 128 rows x 128B
        int slot = tid + 256 * i; int row = slot >> 3, c16 = slot & 7;
        cp16(sbase + SWZ(row * 128 + c16 * 16),
             (const char*)(a0 + (size_t)row * CC) + c16 * 16);
    }
    #pragma unroll
    for (int i = 0; i < 4; i++) {       // B: 128 couts x 128B
        int slot = tid + 256 * i; int row = slot >> 3, c16 = slot & 7;
        cp16(sbase + OFF_B + SWZ(row * 128 + c16 * 16),
             (const char*)(bs + (size_t)row * CIN_K) + c16 * 16);
    }
    asm volatile("cp.async.commit_group;" ::: "memory");
}

__global__ void __launch_bounds__(256, 2)
conv_bf16_kernel(const float* __restrict__ bias, float* __restrict__ out) {
    extern __shared__ __align__(1024) char smem[];
    uint32_t sm = smem_u32(smem);
    int tid = threadIdx.x, wid = tid >> 5, lane = tid & 31;
    int b0  = blockIdx.x * 128;
    int cob = blockIdx.y * 128;
    int n   = blockIdx.z;
    int wm = wid & 3, wn = wid >> 2;    // warp tile: 32 pixels x 64 couts

    float* s_bias  = (float*)(smem + OFF_AB);
    float* s_alpha = (float*)(smem + OFF_AB + 512);
    if (tid < 128) {
        s_bias[tid]  = bias[cob + tid];
        s_alpha[tid] = g_alpha[cob + tid];
    }

    const __nv_bfloat16* aBase = g_xbf + ((size_t)n * XBP_PIX + b0) * CC;
    const __nv_bfloat16* bBase = g_wbf + (size_t)cob * CIN_K;

    int lrow = (lane & 7) + ((lane >> 3) & 1) * 8;
    uint32_t ltb = (uint32_t)((lane >> 4) * 16);
    uint32_t xk  = (uint32_t)((lane & 7) << 4);
    uint32_t aA[2], aB[4];
    #pragma unroll
    for (int mi = 0; mi < 2; mi++) aA[mi] = (uint32_t)((wm * 32 + mi * 16 + lrow) * 128);
    #pragma unroll
    for (int nj = 0; nj < 4; nj++) aB[nj] = (uint32_t)(OFF_B + (wn * 64 + nj * 16 + lrow) * 128);

    float acc[2][8][4];
    #pragma unroll
    for (int mi = 0; mi < 2; mi++)
        #pragma unroll
        for (int ni = 0; ni < 8; ni++)
            #pragma unroll
            for (int j = 0; j < 4; j++) acc[mi][ni][j] = 0.f;

    load_stage_bf(sm + 0 * STAGE, aBase, bBase, 0, tid);
    load_stage_bf(sm + 1 * STAGE, aBase, bBase, 1, tid);

    int slot = 0;
    for (int k = 0; k < NCH; k++) {
        if (k < NCH - 1) asm volatile("cp.async.wait_group 1;" ::: "memory");
        else             asm volatile("cp.async.wait_group 0;" ::: "memory");
        __syncthreads();
        // slot (k+2)%3 == (k-1)%3: finished by all warps before this barrier.
        if (k + 2 < NCH) {
            int s2 = slot + 2; if (s2 >= NSTAGE) s2 -= NSTAGE;
            load_stage_bf(sm + s2 * STAGE, aBase, bBase, k + 2, tid);
        }
        uint32_t sb = sm + slot * STAGE;
        #pragma unroll
        for (int ks = 0; ks < 4; ks++) {                 // 16-ch slices
            uint32_t off = (((uint32_t)(ks << 5)) | ltb) ^ xk;
            uint32_t a[2][4], bf[4][4];
            ldsm4(a[0], sb + aA[0] + off);
            ldsm4(a[1], sb + aA[1] + off);
            #pragma unroll
            for (int nj = 0; nj < 4; nj++) ldsm4(bf[nj], sb + aB[nj] + off);
            #pragma unroll
            for (int mi = 0; mi < 2; mi++)
                #pragma unroll
                for (int ni = 0; ni < 8; ni++) {
                    int nj = ni >> 1, sel = ni & 1;
                    mma_bf16(acc[mi][ni], a[mi], bf[nj][sel], bf[nj][sel + 2]);
                }
        }
        slot = (slot + 1 == NSTAGE) ? 0 : slot + 1;
    }

    #pragma unroll
    for (int mi = 0; mi < 2; mi++)
        #pragma unroll
        for (int half = 0; half < 2; half++) {
            int b = b0 + wm * 32 + mi * 16 + (lane >> 2) + half * 8;
            int h = b / PADW, wp = b % PADW;
            bool valid = (h < HH) && (wp < WW);
            float bm = valid ? g_betamap[(size_t)n * HW + h * WW + wp] : 0.f;
            float* obase = out + (size_t)n * COUT * HW + h * WW + wp;
            if (valid) {
                #pragma unroll
                for (int ni = 0; ni < 8; ni++)
                    #pragma unroll
                    for (int j2 = 0; j2 < 2; j2++) {
                        int col = wn * 64 + ni * 8 + 2 * (lane & 3) + j2;
                        float v = (acc[mi][ni][half * 2 + j2] + s_bias[col])
                                  * bm * s_alpha[col];
                        obase[(size_t)(cob + col) * HW] = fmaxf(v, 0.f);
                    }
            }
        }
}

// ---------------- launcher ----------------
extern "C" void kernel_launch(void* const* d_in, const int* in_sizes, int n_in,
                              void* d_out, int out_size) {
    const float* x       = (const float*)d_in[0];
    const float* gamma   = (const float*)d_in[1];
    const float* beta_bn = (const float*)d_in[2];
    const float* Wt      = (const float*)d_in[3];
    const float* b       = (const float*)d_in[4];
    float* out = (float*)d_out;

    cudaFuncSetAttribute(conv_bf16_kernel,
                         cudaFuncAttributeMaxDynamicSharedMemorySize, SMEM_TOT);

    stats_part_kernel<<<dim3(CC, 8), 256>>>(x);                       // launch 0
    binact_pack_kernel<<<(NHW + 255) / 256, 256>>>(x, gamma, beta_bn); // launch 1
    boxwprep_kernel<<<BOX_BLOCKS + COUT, 256>>>(Wt);                  // launch 2
    conv_bf16_kernel<<<dim3(27, 2, NB), 256, SMEM_TOT>>>(b, out);     // launch 3
}

// round 13
// speedup vs baseline: 1.0478x; 1.0025x over previous
#include <cuda_runtime.h>
#include <cuda_bf16.h>
#include <cstdint>

#define NB   32
#define CC   256
#define HH   56
#define WW   56
#define HW   3136
#define NHW  100352
#define COUT 256
#define KK   9
#define CIN_K 2304
#define PADW 58
#define XBP_PIX 3584

// ---------------- scratch (device globals; zero-init => padding stays 0) -------
__device__ float g_psum[CC * 8 * 2];
__device__ float g_m[NHW];
__device__ float g_betamap[NHW];
__device__ float g_alpha[COUT];
__device__ __nv_bfloat16 g_xbf[(size_t)NB * XBP_PIX * CC];   // [n][padded pix][c]
__device__ __nv_bfloat16 g_wbf[(size_t)COUT * CIN_K];        // [cout][tap*256+ci]

// ---------------- helpers ----------------
__device__ __forceinline__ uint32_t smem_u32(const void* p) {
    uint32_t a;
    asm("{ .reg .u64 t; cvta.to.shared.u64 t, %1; cvt.u32.u64 %0, t; }" : "=r"(a) : "l"(p));
    return a;
}
#define SWZ(o) ((o) ^ (((o) >> 3) & 0x70))
__device__ __forceinline__ void cp16(uint32_t dst, const void* src) {
    asm volatile("cp.async.cg.shared.global [%0], [%1], 16;" :: "r"(dst), "l"(src));
}
__device__ __forceinline__ void ldsm4(uint32_t* r, uint32_t addr) {
    asm volatile("ldmatrix.sync.aligned.m8n8.x4.shared.b16 {%0,%1,%2,%3}, [%4];"
                 : "=r"(r[0]), "=r"(r[1]), "=r"(r[2]), "=r"(r[3]) : "r"(addr));
}
__device__ __forceinline__ void mma_bf16(float* d, const uint32_t* a, uint32_t b0, uint32_t b1) {
    asm volatile("mma.sync.aligned.m16n8k16.row.col.f32.bf16.bf16.f32 "
                 "{%0,%1,%2,%3}, {%4,%5,%6,%7}, {%8,%9}, {%0,%1,%2,%3};"
                 : "+f"(d[0]), "+f"(d[1]), "+f"(d[2]), "+f"(d[3])
                 : "r"(a[0]), "r"(a[1]), "r"(a[2]), "r"(a[3]), "r"(b0), "r"(b1));
}
__device__ __forceinline__ void mbar_init(uint32_t a, uint32_t cnt) {
    asm volatile("mbarrier.init.shared.b64 [%0], %1;" :: "r"(a), "r"(cnt) : "memory");
}
__device__ __forceinline__ void mbar_wait(uint32_t a, uint32_t parity) {
    uint32_t done = 0;
    while (!done) {
        asm volatile(
            "{ .reg .pred p; mbarrier.try_wait.parity.acquire.cta.shared::cta.b64 p, [%1], %2, 0x989680; selp.b32 %0,1,0,p; }"
            : "=r"(done) : "r"(a), "r"(parity) : "memory");
    }
}
__device__ __forceinline__ void mbar_arrive(uint32_t a) {
    asm volatile("mbarrier.arrive.shared.b64 _, [%0];" :: "r"(a) : "memory");
}
__device__ __forceinline__ void cpasync_arrive(uint32_t a) {
    asm volatile("cp.async.mbarrier.arrive.noinc.shared.b64 [%0];" :: "r"(a) : "memory");
}

// ---------------- K1: BN batch partial sums ----------------
__global__ void stats_part_kernel(const float* __restrict__ x) {
    int c = blockIdx.x, sl = blockIdx.y, tid = threadIdx.x;
    float s = 0.f, s2 = 0.f;
    for (int n = sl * 4; n < sl * 4 + 4; n++) {
        const float* p = x + ((size_t)n * CC + c) * HW;
        for (int i = tid; i < HW; i += blockDim.x) { float v = p[i]; s += v; s2 += v * v; }
    }
    __shared__ float sh[256], sh2[256];
    sh[tid] = s; sh2[tid] = s2; __syncthreads();
    for (int off = 128; off > 0; off >>= 1) {
        if (tid < off) { sh[tid] += sh[tid + off]; sh2[tid] += sh2[tid + off]; }
        __syncthreads();
    }
    if (tid == 0) { g_psum[(c * 8 + sl) * 2] = sh[0]; g_psum[(c * 8 + sl) * 2 + 1] = sh2[0]; }
}

// ------- K2: finalize stats in-block, binarize -> bf16 padded, + |xn| mean -----
__global__ void binact_pack_kernel(const float* __restrict__ x,
                                   const float* __restrict__ gamma,
                                   const float* __restrict__ beta_bn) {
    __shared__ float s_scale[CC], s_shift[CC];
    {
        int c = threadIdx.x;
        float s = 0.f, s2 = 0.f;
        #pragma unroll
        for (int i = 0; i < 8; i++) {
            s  += g_psum[(c * 8 + i) * 2];
            s2 += g_psum[(c * 8 + i) * 2 + 1];
        }
        float mu  = s * (1.0f / (float)NHW);
        float var = s2 * (1.0f / (float)NHW) - mu * mu;
        float inv = rsqrtf(var + 1e-4f);
        float sc  = gamma[c] * inv;
        s_scale[c] = sc;
        s_shift[c] = beta_bn[c] - mu * sc;
    }
    __syncthreads();

    int gp = blockIdx.x * blockDim.x + threadIdx.x;
    if (gp >= NHW) return;
    int n = gp / HW, p = gp % HW;
    int h = p / WW, w = p % WW;
    const float* xp = x + (size_t)n * CC * HW + p;
    __nv_bfloat16* dst = g_xbf + ((size_t)n * XBP_PIX + (h + 1) * PADW + (w + 1)) * CC;
    float acc = 0.f;
    for (int c0 = 0; c0 < CC; c0 += 64) {
        __nv_bfloat16 bbuf[64];
        #pragma unroll
        for (int cc = 0; cc < 64; cc++) {
            int c = c0 + cc;
            float v = xp[(size_t)c * HW] * s_scale[c] + s_shift[c];
            acc += fabsf(v);
            float s = (v > 0.f) ? 1.f : ((v < 0.f) ? -1.f : 0.f);
            bbuf[cc] = __float2bfloat16(s);
        }
        #pragma unroll
        for (int i = 0; i < 8; i++)
            reinterpret_cast<uint4*>(dst + c0)[i] = reinterpret_cast<uint4*>(bbuf)[i];
    }
    g_m[gp] = acc * (1.0f / (float)CC);
}

// ------- K3: box filter + weight prep (bf16, tap-major) + alpha ----------------
#define BOX_BLOCKS ((NHW + 255) / 256)
__global__ void boxwprep_kernel(const float* __restrict__ Wt) {
    if (blockIdx.x < BOX_BLOCKS) {
        int gp = blockIdx.x * blockDim.x + threadIdx.x;
        if (gp >= NHW) return;
        int n = gp / HW, p = gp % HW;
        int h = p / WW, w = p % WW;
        const float* mp = g_m + (size_t)n * HW;
        float s = 0.f;
        #pragma unroll
        for (int dh = -1; dh <= 1; dh++)
            #pragma unroll
            for (int dw = -1; dw <= 1; dw++) {
                int hh = h + dh, ww2 = w + dw;
                if (hh >= 0 && hh < HH && ww2 >= 0 && ww2 < WW) s += mp[hh * WW + ww2];
            }
        g_betamap[gp] = s * (1.0f / 9.0f);
    } else {
        int co = blockIdx.x - BOX_BLOCKS, tid = threadIdx.x;
        const float* wp = Wt + (size_t)co * CIN_K;
        float s = 0.f;
        for (int i = tid; i < CIN_K; i += blockDim.x) {
            float v = wp[i];
            s += fabsf(v);
            int ci = i / KK, tap = i % KK;
            float sv = (v > 0.f) ? 1.f : ((v < 0.f) ? -1.f : 0.f);
            g_wbf[(size_t)co * CIN_K + tap * CC + ci] = __float2bfloat16(sv);
        }
        __shared__ float sh[256];
        sh[tid] = s; __syncthreads();
        for (int off = 128; off > 0; off >>= 1) {
            if (tid < off) sh[tid] += sh[tid + off];
            __syncthreads();
        }
        if (tid == 0) g_alpha[co] = sh[0] * (1.0f / (float)CIN_K);
    }
}

// ------ K4: bf16 HMMA conv, warp-granular mbarrier pipeline --------------------
#define STAGE 32768          // A 16KB + B 16KB
#define OFF_B 16384
#define NSTAGE 3
#define NCH 36               // 9 taps x 4 chunks of 64 channels
#define OFF_MB (NSTAGE * STAGE)              // 98304: 3 x (full,empty) pairs
#define OFF_AB (OFF_MB + 128)
#define SMEM_TOT (OFF_AB + 1024)
#define MB_FULL(s)  (OFF_MB + (s) * 16)
#define MB_EMPTY(s) (OFF_MB + (s) * 16 + 8)

__device__ __forceinline__ void load_stage_bf(uint32_t sbase, const __nv_bfloat16* aBase,
                                              const __nv_bfloat16* bBase, int chunk, int tid) {
    int t = chunk >> 2, q = chunk & 3;                   // tap, 64-channel group
    int off_t = (t / 3) * PADW + (t % 3);
    const __nv_bfloat16* a0 = aBase + (size_t)off_t * CC + q * 64;
    const __nv_bfloat16* bs = bBase + t * CC + q * 64;
    #pragma unroll
    for (int i = 0; i < 4; i++) {       // A: 128 rows x 128B
        int slot = tid + 256 * i; int row = slot >> 3, c16 = slot & 7;
        cp16(sbase + SWZ(row * 128 + c16 * 16),
             (const char*)(a0 + (size_t)row * CC) + c16 * 16);
    }
    #pragma unroll
    for (int i = 0; i < 4; i++) {       // B: 128 couts x 128B
        int slot = tid + 256 * i; int row = slot >> 3, c16 = slot & 7;
        cp16(sbase + OFF_B + SWZ(row * 128 + c16 * 16),
             (const char*)(bs + (size_t)row * CIN_K) + c16 * 16);
    }
}

__global__ void __launch_bounds__(256, 2)
conv_bf16_kernel(const float* __restrict__ bias, float* __restrict__ out) {
    extern __shared__ __align__(1024) char smem[];
    uint32_t sm = smem_u32(smem);
    int tid = threadIdx.x, wid = tid >> 5, lane = tid & 31;
    int b0  = blockIdx.x * 128;
    int cob = blockIdx.y * 128;
    int n   = blockIdx.z;
    int wm = wid & 3, wn = wid >> 2;    // warp tile: 32 pixels x 64 couts

    float* s_bias  = (float*)(smem + OFF_AB);
    float* s_alpha = (float*)(smem + OFF_AB + 512);
    if (tid < 128) {
        s_bias[tid]  = bias[cob + tid];
        s_alpha[tid] = g_alpha[cob + tid];
    }
    if (tid == 0) {
        #pragma unroll
        for (int s = 0; s < NSTAGE; s++) {
            mbar_init(sm + MB_FULL(s), 256);   // cp.async arrive per thread
            mbar_init(sm + MB_EMPTY(s), 8);    // one arrive per warp
        }
    }
    __syncthreads();

    const __nv_bfloat16* aBase = g_xbf + ((size_t)n * XBP_PIX + b0) * CC;
    const __nv_bfloat16* bBase = g_wbf + (size_t)cob * CIN_K;

    int lrow = (lane & 7) + ((lane >> 3) & 1) * 8;
    uint32_t ltb = (uint32_t)((lane >> 4) * 16);
    uint32_t xk  = (uint32_t)((lane & 7) << 4);
    uint32_t aA[2], aB[4];
    #pragma unroll
    for (int mi = 0; mi < 2; mi++) aA[mi] = (uint32_t)((wm * 32 + mi * 16 + lrow) * 128);
    #pragma unroll
    for (int nj = 0; nj < 4; nj++) aB[nj] = (uint32_t)(OFF_B + (wn * 64 + nj * 16 + lrow) * 128);

    float acc[2][8][4];
    #pragma unroll
    for (int mi = 0; mi < 2; mi++)
        #pragma unroll
        for (int ni = 0; ni < 8; ni++)
            #pragma unroll
            for (int j = 0; j < 4; j++) acc[mi][ni][j] = 0.f;

    // producer cursor (phase 1: first empty-waits on fresh barriers pass),
    // consumer cursor (phase 0)
    int pslot = 0, pphase = 1, cslot = 0, cphase = 0;

    // prologue: produce chunks 0 and 1
    #pragma unroll
    for (int j = 0; j < 2; j++) {
        mbar_wait(sm + MB_EMPTY(pslot), (uint32_t)pphase);
        load_stage_bf(sm + pslot * STAGE, aBase, bBase, j, tid);
        cpasync_arrive(sm + MB_FULL(pslot));
        if (++pslot == NSTAGE) { pslot = 0; pphase ^= 1; }
    }

    for (int k = 0; k < NCH; k++) {
        if (k + 2 < NCH) {
            mbar_wait(sm + MB_EMPTY(pslot), (uint32_t)pphase);
            load_stage_bf(sm + pslot * STAGE, aBase, bBase, k + 2, tid);
            cpasync_arrive(sm + MB_FULL(pslot));
            if (++pslot == NSTAGE) { pslot = 0; pphase ^= 1; }
        }
        mbar_wait(sm + MB_FULL(cslot), (uint32_t)cphase);
        uint32_t sb = sm + cslot * STAGE;
        #pragma unroll
        for (int ks = 0; ks < 4; ks++) {                 // 16-ch slices
            uint32_t off = (((uint32_t)(ks << 5)) | ltb) ^ xk;
            uint32_t a[2][4], bf[4][4];
            ldsm4(a[0], sb + aA[0] + off);
            ldsm4(a[1], sb + aA[1] + off);
            #pragma unroll
            for (int nj = 0; nj < 4; nj++) ldsm4(bf[nj], sb + aB[nj] + off);
            #pragma unroll
            for (int mi = 0; mi < 2; mi++)
                #pragma unroll
                for (int ni = 0; ni < 8; ni++) {
                    int nj = ni >> 1, sel = ni & 1;
                    mma_bf16(acc[mi][ni], a[mi], bf[nj][sel], bf[nj][sel + 2]);
                }
        }
        __syncwarp();
        if (lane == 0) mbar_arrive(sm + MB_EMPTY(cslot));
        if (++cslot == NSTAGE) { cslot = 0; cphase ^= 1; }
    }

    #pragma unroll
    for (int mi = 0; mi < 2; mi++)
        #pragma unroll
        for (int half = 0; half < 2; half++) {
            int b = b0 + wm * 32 + mi * 16 + (lane >> 2) + half * 8;
            int h = b / PADW, wp = b % PADW;
            bool valid = (h < HH) && (wp < WW);
            float bm = valid ? g_betamap[(size_t)n * HW + h * WW + wp] : 0.f;
            float* obase = out + (size_t)n * COUT * HW + h * WW + wp;
            if (valid) {
                #pragma unroll
                for (int ni = 0; ni < 8; ni++)
                    #pragma unroll
                    for (int j2 = 0; j2 < 2; j2++) {
                        int col = wn * 64 + ni * 8 + 2 * (lane & 3) + j2;
                        float v = (acc[mi][ni][half * 2 + j2] + s_bias[col])
                                  * bm * s_alpha[col];
                        obase[(size_t)(cob + col) * HW] = fmaxf(v, 0.f);
                    }
            }
        }
}

// ---------------- launcher ----------------
extern "C" void kernel_launch(void* const* d_in, const int* in_sizes, int n_in,
                              void* d_out, int out_size) {
    const float* x       = (const float*)d_in[0];
    const float* gamma   = (const float*)d_in[1];
    const float* beta_bn = (const float*)d_in[2];
    const float* Wt      = (const float*)d_in[3];
    const float* b       = (const float*)d_in[4];
    float* out = (float*)d_out;

    cudaFuncSetAttribute(conv_bf16_kernel,
                         cudaFuncAttributeMaxDynamicSharedMemorySize, SMEM_TOT);

    stats_part_kernel<<<dim3(CC, 8), 256>>>(x);                        // launch 0
    binact_pack_kernel<<<(NHW + 255) / 256, 256>>>(x, gamma, beta_bn); // launch 1
    boxwprep_kernel<<<BOX_BLOCKS + COUT, 256>>>(Wt);                   // launch 2
    conv_bf16_kernel<<<dim3(27, 2, NB), 256, SMEM_TOT>>>(b, out);      // launch 3
}